// round 5
// baseline (speedup 1.0000x reference)
#include <cuda_runtime.h>

// Heirachical_Loss — closed-form collapse of the hierarchy matmul.
//
// loss = B - sum_i [ 0.5*S_all + 0.25*S100(t) + 0.125*S10(t) + 0.125*outputs[i,t] ]
//
// Layout: one warp per row (best measured MLP), fused deterministic
// last-block final reduce (fixed order, no float atomics; counter
// auto-wraps so graph replays are self-resetting).
// s100 is computed from the registers already holding the row (the
// 100-block is exactly 25 aligned float4s) — no bulk re-read. Only the
// 10-block needs a tiny 3-float4 L1-hit re-read on lanes 0-2.

#define HL_C            1000
#define WARPS_PER_BLOCK 8
#define HL_THREADS      256
#define MAX_BLOCKS      8192   // supports B up to 65536 rows

__device__ float        g_hl_partials[MAX_BLOCKS];
__device__ unsigned int g_hl_count = 0;

__global__ void __launch_bounds__(HL_THREADS) hloss_fused(
    const float* __restrict__ outputs,
    const int*   __restrict__ target,
    float*       __restrict__ out,
    int B)
{
    const int warp = threadIdx.x >> 5;
    const int lane = threadIdx.x & 31;
    const int row  = blockIdx.x * WARPS_PER_BLOCK + warp;

    float part = 0.0f;   // per-lane partial of win(row)
    if (row < B) {
        const int t = target[row];
        const float4* __restrict__ p =
            (const float4*)(outputs + (size_t)row * HL_C);

        const int q0   = ((t / 100) * 100) >> 2;   // 100-block = float4 [q0, q0+25)
        const int lo10 = (t / 10) * 10;
        const int f10  = lo10 >> 2;                // 3 float4s cover the 10-block

        // ---- Front-batch all loads for this row (MLP ~ 9) ----
        float4 v[7];
#pragma unroll
        for (int it = 0; it < 7; ++it)
            v[it] = p[it * 32 + lane];                    // float4 idx 0..223
        float4 vt = make_float4(0.f, 0.f, 0.f, 0.f);
        if (lane < 26) vt = p[224 + lane];                // idx 224..249
        float4 q3 = make_float4(0.f, 0.f, 0.f, 0.f);
        if (lane < 3)  q3 = p[f10 + lane];                // 10-block cover (L1 hit)

        // ---- Row sum + in-register 100-block sum ----
        float s = 0.f, s100 = 0.f;
#pragma unroll
        for (int it = 0; it < 7; ++it) {
            const float sum4 = (v[it].x + v[it].y) + (v[it].z + v[it].w);
            s += sum4;
            if ((unsigned)(it * 32 + lane - q0) < 25u) s100 += sum4;
        }
        {
            const float sum4 = (vt.x + vt.y) + (vt.z + vt.w); // 0 for lane>=26
            s += sum4;
            if ((unsigned)(224 + lane - q0) < 25u) s100 += sum4;
        }

        // ---- 10-block sum + target element (lanes 0-2 hold real data) ----
        float s10 = 0.f, ot = 0.f;
        {
            const float vals[4] = { q3.x, q3.y, q3.z, q3.w };
            const int e0 = (f10 + lane) * 4;
#pragma unroll
            for (int m = 0; m < 4; ++m) {
                const int e = e0 + m;
                if ((unsigned)(e - lo10) < 10u) s10 += vals[m];
                if (e == t)                     ot   = vals[m];
            }
        }

        part = 0.5f * s + 0.25f * s100 + 0.125f * s10 + 0.125f * ot;
    }

    // ---- Warp reduce: part -> win(row), lane-uniform ----
#pragma unroll
    for (int off = 16; off; off >>= 1)
        part += __shfl_xor_sync(0xffffffffu, part, off);

    // ---- Block reduce: one (1 - win) per warp ----
    __shared__ float ws[WARPS_PER_BLOCK];
    __shared__ bool  s_is_last;
    if (lane == 0)
        ws[warp] = (row < B) ? (1.0f - part) : 0.0f;
    __syncthreads();
    if (threadIdx.x == 0) {
        float bsum = 0.f;
#pragma unroll
        for (int w = 0; w < WARPS_PER_BLOCK; ++w) bsum += ws[w];
        g_hl_partials[blockIdx.x] = bsum;
        __threadfence();
        // atomicInc wraps to 0 when old == gridDim.x-1 -> auto-reset per replay.
        unsigned vcnt = atomicInc(&g_hl_count, gridDim.x - 1u);
        s_is_last = (vcnt == gridDim.x - 1u);
    }
    __syncthreads();

    // ---- Last block: deterministic fixed-order final sum ----
    if (s_is_last) {
        __threadfence();
        float a = 0.f;
        for (int i = threadIdx.x; i < (int)gridDim.x; i += HL_THREADS)
            a += g_hl_partials[i];
        __shared__ float sm[HL_THREADS];
        sm[threadIdx.x] = a;
        __syncthreads();
#pragma unroll
        for (int s2 = HL_THREADS / 2; s2; s2 >>= 1) {
            if (threadIdx.x < s2) sm[threadIdx.x] += sm[threadIdx.x + s2];
            __syncthreads();
        }
        if (threadIdx.x == 0) out[0] = sm[0];
    }
}

extern "C" void kernel_launch(void* const* d_in, const int* in_sizes, int n_in,
                              void* d_out, int out_size)
{
    // metadata order: outputs [B*1000] float32, target [B] int32.
    int i_o = 0, i_t = 1;
    if (n_in >= 2 && in_sizes[1] > in_sizes[0]) { i_o = 1; i_t = 0; }

    const float* outputs = (const float*)d_in[i_o];
    const int*   target  = (const int*)d_in[i_t];
    const int B = in_sizes[i_t];

    int nblocks = (B + WARPS_PER_BLOCK - 1) / WARPS_PER_BLOCK;  // 4096 for B=32768
    if (nblocks > MAX_BLOCKS) nblocks = MAX_BLOCKS;

    hloss_fused<<<nblocks, HL_THREADS>>>(outputs, target, (float*)d_out, B);
}